// round 4
// baseline (speedup 1.0000x reference)
#include <cuda_runtime.h>

// MultiScaleProcessor: images[64,256,256,3] f32 -> out[64,4,256,256,3] f32
// Scales (sorted): 32, 64, 128, 256. Bilinear resize (linspace coords, edge
// clamp), zero-pad centered to 256x256. Scale 256 = passthrough copy.
//
// Structure: one block = 8 consecutive output rows of one (batch, scale)
// image = one contiguous 24 KB store region.
//  - p and p+s are multiples of 8 for all scales -> each block is uniformly
//    zero-band or data-band (no per-row classification).
//  - one row = 768 floats = 192 float4; pad boundaries in floats are
//    multiples of 4 -> every float4 is all-zero or all-data (STG.128 only).
//  - default store policy (R3 showed .cs streaming stores cost ~12%).

#define ROWS_PER_BLK 8

__global__ void __launch_bounds__(192) msp_kernel(const float* __restrict__ in,
                                                  float* __restrict__ out) {
    const int t  = threadIdx.x;                  // float4 column 0..191
    const int yb = blockIdx.x * ROWS_PER_BLK;    // first row of block
    const int si = blockIdx.y;                   // scale = 32<<si
    const int b  = blockIdx.z;

    const int s = 32 << si;
    const int p = (256 - s) >> 1;

    const float* ib = in + (size_t)b * (256 * 256 * 3);
    float4* obase = reinterpret_cast<float4*>(
        out + (((size_t)b * 4 + si) * 256 + yb) * 768) + t;

    // ---------- native-resolution passthrough: vector copy ----------
    if (si == 3) {
        const float4* irow = reinterpret_cast<const float4*>(ib + yb * 768) + t;
        float4 v[ROWS_PER_BLK];
#pragma unroll
        for (int r = 0; r < ROWS_PER_BLK; r++) v[r] = __ldg(irow + r * 192);
#pragma unroll
        for (int r = 0; r < ROWS_PER_BLK; r++) obase[r * 192] = v[r];
        return;
    }

    const float4 z = make_float4(0.f, 0.f, 0.f, 0.f);
    const int g0 = 4 * t;            // first float index this thread owns
    const int lo = 3 * p;            // data region [lo, hi) in floats
    const int hi = 3 * (p + s);

    // ---------- padding band (whole block) or side padding (thread) ----
    const bool zero_rows = (yb < p) | (yb >= p + s);
    const bool in_band   = (g0 >= lo) & (g0 < hi);
    if (zero_rows || !in_band) {
#pragma unroll
        for (int r = 0; r < ROWS_PER_BLK; r++) obase[r * 192] = z;
        return;
    }

    // ---------- data band: bilinear ----------
    const float fac = 255.0f / (float)(s - 1);

    // x-interp constants are row-invariant
    int   x0k[4], x1k[4];
    float wxk[4];
#pragma unroll
    for (int k = 0; k < 4; k++) {
        const int rel = g0 + k - lo;
        const int xx  = rel / 3;
        const int c   = rel - 3 * xx;
        const float fx = (float)xx * fac;
        const int x0 = (int)fx;
        wxk[k] = fx - (float)x0;
        x0k[k] = x0 * 3 + c;
        x1k[k] = min(x0 + 1, 255) * 3 + c;
    }

#pragma unroll
    for (int r = 0; r < ROWS_PER_BLK; r++) {
        const int y  = yb + r;
        const int iy = y - p;
        const float fy = (float)iy * fac;
        const int   y0 = (int)fy;
        const float wy = fy - (float)y0;
        const int   y1 = min(y0 + 1, 255);

        const float* __restrict__ r0 = ib + y0 * 768;
        const float* __restrict__ r1 = ib + y1 * 768;

        float res[4];
#pragma unroll
        for (int k = 0; k < 4; k++) {
            const float a  = __ldg(r0 + x0k[k]);
            const float bb = __ldg(r0 + x1k[k]);
            const float cc = __ldg(r1 + x0k[k]);
            const float d  = __ldg(r1 + x1k[k]);
            const float top = a  + (bb - a ) * wxk[k];
            const float bot = cc + (d  - cc) * wxk[k];
            res[k] = top + (bot - top) * wy;
        }
        obase[r * 192] = make_float4(res[0], res[1], res[2], res[3]);
    }
}

extern "C" void kernel_launch(void* const* d_in, const int* in_sizes, int n_in,
                              void* d_out, int out_size) {
    const float* in = (const float*)d_in[0];
    float* out = (float*)d_out;
    dim3 grid(256 / ROWS_PER_BLK, 4, 64);   // 8192 blocks
    msp_kernel<<<grid, 192>>>(in, out);
}

// round 5
// speedup vs baseline: 1.2107x; 1.2107x over previous
#include <cuda_runtime.h>

// MultiScaleProcessor: images[64,256,256,3] f32 -> out[64,4,256,256,3] f32
// Scales (sorted): 32, 64, 128, 256. Bilinear resize (linspace coords, edge
// clamp), zero-pad centered to 256x256. Scale 256 = passthrough copy.
//
// R2 structure (best measured: 43.2us kernel): 2 rows/block, load/store
// interleaved per row (keeps MLP_p1 low -> avoids cross-CTA L1tex-queue
// spread that regressed the 8-row variants). This round's change:
// __launch_bounds__(192, 10) to force regs<=32 -> 10 blocks/SM (93.75%
// theoretical occupancy, was 75% at regs=40).

#define ROWS_PER_BLK 2

__global__ void __launch_bounds__(192, 10) msp_kernel(const float* __restrict__ in,
                                                      float* __restrict__ out) {
    const int t   = threadIdx.x;                 // float4 index within row 0..191
    const int yb  = blockIdx.x * ROWS_PER_BLK;   // first row of this block
    const int si  = blockIdx.y;                  // 0..3  (scale = 32<<si)
    const int b   = blockIdx.z;                  // 0..63

    const int s = 32 << si;
    const int p = (256 - s) >> 1;

    const float* ib = in + (size_t)b * (256 * 256 * 3);
    float4* obase = reinterpret_cast<float4*>(
        out + (((size_t)b * 4 + si) * 256) * 768);

    const float fac = 255.0f / (float)(s - 1);
    const int g0 = 4 * t;          // first float index this thread owns in a row
    const int lo = 3 * p;          // data region [lo, hi) in floats
    const int hi = 3 * (p + s);

    // Per-thread x-interp constants are row-invariant: precompute once.
    int   x0k[4], x1k[4];
    float wxk[4];
    const bool in_band = (g0 >= lo) & (g0 < hi);
    if (si != 3 && in_band) {
#pragma unroll
        for (int k = 0; k < 4; k++) {
            const int rel = g0 + k - lo;
            const int xx  = rel / 3;
            const int c   = rel - 3 * xx;
            const float fx = (float)xx * fac;
            const int x0 = (int)fx;
            wxk[k] = fx - (float)x0;
            x0k[k] = x0 * 3 + c;
            x1k[k] = min(x0 + 1, 255) * 3 + c;
        }
    }

    const float4 z = make_float4(0.f, 0.f, 0.f, 0.f);

#pragma unroll
    for (int r = 0; r < ROWS_PER_BLK; r++) {
        const int y = yb + r;
        float4* orow = obase + (size_t)y * 192;

        if (si == 3) {
            // passthrough: load/store interleaved (MLP_p1 stays ~1)
            const float4* irow = reinterpret_cast<const float4*>(ib + y * 768);
            orow[t] = irow[t];
            continue;
        }
        if (y < p || y >= p + s || !in_band) { orow[t] = z; continue; }

        // bilinear y setup (matches jnp.linspace(0, 255, s) coords)
        const int   iy = y - p;
        const float fy = (float)iy * fac;
        const int   y0 = (int)fy;
        const float wy = fy - (float)y0;
        const int   y1 = min(y0 + 1, 255);

        const float* __restrict__ r0 = ib + y0 * 768;
        const float* __restrict__ r1 = ib + y1 * 768;

        float res[4];
#pragma unroll
        for (int k = 0; k < 4; k++) {
            const float a  = __ldg(r0 + x0k[k]);
            const float bb = __ldg(r0 + x1k[k]);
            const float cc = __ldg(r1 + x0k[k]);
            const float d  = __ldg(r1 + x1k[k]);
            const float top = a  + (bb - a ) * wxk[k];
            const float bot = cc + (d  - cc) * wxk[k];
            res[k] = top + (bot - top) * wy;
        }
        orow[t] = make_float4(res[0], res[1], res[2], res[3]);
    }
}

extern "C" void kernel_launch(void* const* d_in, const int* in_sizes, int n_in,
                              void* d_out, int out_size) {
    const float* in = (const float*)d_in[0];
    float* out = (float*)d_out;
    dim3 grid(256 / ROWS_PER_BLK, 4, 64);   // 32768 blocks
    msp_kernel<<<grid, 192>>>(in, out);
}

// round 7
// speedup vs baseline: 1.2571x; 1.0384x over previous
#include <cuda_runtime.h>

// MultiScaleProcessor: images[64,256,256,3] f32 -> out[64,4,256,256,3] f32
// Scales (sorted): 32, 64, 128, 256. Bilinear (linspace coords, edge clamp),
// zero-pad centered to 256x256. Scale 256 = passthrough.
//
// R6 (resubmit after infra flake): channel-planar SMEM staging for the gather.
// Data blocks coalesced-load their 4 source input rows into sp[row][c][256]
// SMEM planes, then do bilinear gathers as LDS (pixel-stride addressing, low
// conflict) instead of 16 scattered scalar LDGs per thread (the measured
// limiter: L1=61.5% with time flat across occ 54->75%).

#define ROWS_PER_BLK 2

__global__ void __launch_bounds__(192, 8) msp_kernel(const float* __restrict__ in,
                                                     float* __restrict__ out) {
    __shared__ float sp[4][3][256];   // 12 KB: 4 staged rows, channel-planar

    const int t  = threadIdx.x;                // float4 column 0..191
    const int yb = blockIdx.x * ROWS_PER_BLK;  // first output row
    const int si = blockIdx.y;                 // scale = 32<<si
    const int b  = blockIdx.z;

    const int s = 32 << si;
    const int p = (256 - s) >> 1;

    const float* ib = in + (size_t)b * (256 * 256 * 3);
    float4* obase = reinterpret_cast<float4*>(
        out + (((size_t)b * 4 + si) * 256) * 768);

    // ---------------- native passthrough ----------------
    if (si == 3) {
#pragma unroll
        for (int r = 0; r < ROWS_PER_BLK; r++) {
            const int y = yb + r;
            const float4* irow = reinterpret_cast<const float4*>(ib + y * 768);
            obase[(size_t)y * 192 + t] = irow[t];
        }
        return;
    }

    const float4 z = make_float4(0.f, 0.f, 0.f, 0.f);

    // ---------------- uniform zero-row blocks (p is even for all scales) ----
    if (yb < p || yb >= p + s) {
#pragma unroll
        for (int r = 0; r < ROWS_PER_BLK; r++)
            obase[(size_t)(yb + r) * 192 + t] = z;
        return;
    }

    // ---------------- data block ----------------
    const float fac = 255.0f / (float)(s - 1);

    // source rows for the 2 output rows
    int   Y[4];
    float wyr[2];
#pragma unroll
    for (int r = 0; r < 2; r++) {
        const float fy = (float)(yb + r - p) * fac;
        const int   y0 = (int)fy;
        wyr[r] = fy - (float)y0;
        Y[2 * r]     = y0;
        Y[2 * r + 1] = min(y0 + 1, 255);
    }

    // stage 4 input rows into channel-planar SMEM (coalesced float4 reads)
    {
        const int f0 = 4 * t;
        const int px0 = f0 / 3, c0 = f0 - 3 * px0;
        const int f1 = f0 + 1, px1 = f1 / 3, c1 = f1 - 3 * px1;
        const int f2 = f0 + 2, px2 = f2 / 3, c2 = f2 - 3 * px2;
        const int f3 = f0 + 3, px3 = f3 / 3, c3 = f3 - 3 * px3;
#pragma unroll
        for (int j = 0; j < 4; j++) {
            const float4 v = *(reinterpret_cast<const float4*>(ib + Y[j] * 768) + t);
            sp[j][c0][px0] = v.x;
            sp[j][c1][px1] = v.y;
            sp[j][c2][px2] = v.z;
            sp[j][c3][px3] = v.w;
        }
    }
    __syncthreads();

    const int g0 = 4 * t;
    const int lo = 3 * p;
    const int hi = 3 * (p + s);

    // side-padding threads: zero stores (after the staging sync)
    if (g0 < lo || g0 >= hi) {
#pragma unroll
        for (int r = 0; r < 2; r++)
            obase[(size_t)(yb + r) * 192 + t] = z;
        return;
    }

    // per-thread x constants (row-invariant), pixel-indexed
    int   pxa[4], pxb[4], cc[4];
    float wxk[4];
#pragma unroll
    for (int k = 0; k < 4; k++) {
        const int rel = g0 + k - lo;
        const int xx  = rel / 3;
        cc[k] = rel - 3 * xx;
        const float fx = (float)xx * fac;
        const int x0 = (int)fx;
        wxk[k] = fx - (float)x0;
        pxa[k] = x0;
        pxb[k] = min(x0 + 1, 255);
    }

#pragma unroll
    for (int r = 0; r < 2; r++) {
        const float wy = wyr[r];
        float res[4];
#pragma unroll
        for (int k = 0; k < 4; k++) {
            const float a  = sp[2 * r    ][cc[k]][pxa[k]];
            const float bb = sp[2 * r    ][cc[k]][pxb[k]];
            const float c2 = sp[2 * r + 1][cc[k]][pxa[k]];
            const float d  = sp[2 * r + 1][cc[k]][pxb[k]];
            const float top = a  + (bb - a ) * wxk[k];
            const float bot = c2 + (d  - c2) * wxk[k];
            res[k] = top + (bot - top) * wy;
        }
        obase[(size_t)(yb + r) * 192 + t] =
            make_float4(res[0], res[1], res[2], res[3]);
    }
}

extern "C" void kernel_launch(void* const* d_in, const int* in_sizes, int n_in,
                              void* d_out, int out_size) {
    const float* in = (const float*)d_in[0];
    float* out = (float*)d_out;
    dim3 grid(256 / ROWS_PER_BLK, 4, 64);   // 32768 blocks
    msp_kernel<<<grid, 192>>>(in, out);
}